// round 16
// baseline (speedup 1.0000x reference)
#include <cuda_runtime.h>

// Problem constants
#define TBm 32       // T*B
#define Cc  256
#define Nn  196
#define Hh  16
#define Dd  16
#define HDd 1024
#define Jj  (TBm*Nn)        // 6272
#define NC  (TBm*Cc*Nn)     // 1,605,632
#define NHD (TBm*HDd*Nn)    // 6,422,528
#define MASKN (TBm*Hh*Nn)   // 100,352
#define EPSV 1e-5f

// ---------------- scratch (static device globals; no runtime alloc) -------------
__device__ float g_z [6*NC];         // 6 qkv buffers; also >= NHD for m1 scratch
__device__ float g_h [NHD];          // h spikes (m1 output)
__device__ float g_s [2*NC];         // attention o spikes (both sca branches)
__device__ float g_x1[NC];
__device__ float g_y1[NC];
__device__ float g_cur[NC];
__device__ unsigned int g_mask[6*MASKN];
__device__ float g_mu[6*Cc >= HDd ? 6*Cc : HDd];
__device__ float g_rs[6*Cc >= HDd ? 6*Cc : HDd];

// BN affine exactly as reference: ((g*(z-mu))*rs)+b, separate roundings
__device__ __forceinline__ float bn_val(float v, float g, float mu, float rs, float b)
{
    return __fadd_rn(__fmul_rn(__fmul_rn(g, __fsub_rn(v, mu)), rs), b);
}

// ---------------- GEMM core: out[m,d,n] = sum_c W[d,c]*A[m,c,n] ----------------
// Exact fp32, strictly ascending-k single-accumulator FMA per output element.
// Tile 64(d) x 64(j), BK=16, 128 threads, 8x4 per thread; register prefetch.
__device__ __forceinline__ void gemm_body(
    const float* __restrict__ A, const float* __restrict__ W,
    const float* __restrict__ bias,
    float* __restrict__ out, int Cin, int Cout)
{
    __shared__ float As[16][68];
    __shared__ float Bs[16][68];
    const int t  = threadIdx.x;
    const int d0 = blockIdx.y * 64;
    const int j0 = blockIdx.x * 64;
    const int tx = t & 15;           // j group: j = j0 + tx*4 .. +3
    const int ty = t >> 4;           // d group: d = d0 + ty*8 .. +7
    const int jj = t & 63;
    const int kr = t >> 6;           // 0..1  (k rows kr + 2*r, r<8)
    const int jB = j0 + jj;
    const int mB = jB / Nn;
    const int nB = jB - mB * Nn;
    const int kc = t & 15;           // k column
    const int dr = t >> 4;           // 0..7  (d rows dr + 8*r, r<8)

    float acc[8][4];
#pragma unroll
    for (int i = 0; i < 8; i++)
#pragma unroll
        for (int q = 0; q < 4; q++) acc[i][q] = 0.f;

    float wreg[8], breg[8];
    const float* aptr = A + (size_t)mB * Cin * Nn + nB;
    const int nst = Cin >> 4;

    // prefetch stage 0
#pragma unroll
    for (int r = 0; r < 8; ++r)
        wreg[r] = W[(size_t)(d0 + dr + 8*r) * Cin + kc];
#pragma unroll
    for (int r = 0; r < 8; ++r)
        breg[r] = aptr[(size_t)(kr + 2*r) * Nn];

#pragma unroll 1
    for (int s = 0; s < nst; ++s) {
        __syncthreads();
#pragma unroll
        for (int r = 0; r < 8; ++r) As[kc][dr + 8*r] = wreg[r];
#pragma unroll
        for (int r = 0; r < 8; ++r) Bs[kr + 2*r][jj] = breg[r];
        __syncthreads();

        if (s + 1 < nst) {
            const int c0 = (s + 1) << 4;
#pragma unroll
            for (int r = 0; r < 8; ++r)
                wreg[r] = W[(size_t)(d0 + dr + 8*r) * Cin + c0 + kc];
#pragma unroll
            for (int r = 0; r < 8; ++r)
                breg[r] = aptr[(size_t)(c0 + kr + 2*r) * Nn];
        }
#pragma unroll
        for (int k = 0; k < 16; ++k) {
            float4 a0 = *reinterpret_cast<const float4*>(&As[k][ty * 8]);
            float4 a1 = *reinterpret_cast<const float4*>(&As[k][ty * 8 + 4]);
            float4 b4 = *reinterpret_cast<const float4*>(&Bs[k][tx * 4]);
            float a[8] = {a0.x, a0.y, a0.z, a0.w, a1.x, a1.y, a1.z, a1.w};
            float b[4] = {b4.x, b4.y, b4.z, b4.w};
#pragma unroll
            for (int i = 0; i < 8; i++)
#pragma unroll
                for (int q = 0; q < 4; q++)
                    acc[i][q] = __fmaf_rn(a[i], b[q], acc[i][q]);
        }
    }
#pragma unroll
    for (int q = 0; q < 4; q++) {
        int jw = j0 + tx * 4 + q;
        int mo = jw / Nn;
        int no = jw - mo * Nn;
        float* obase = out + (size_t)mo * Cout * Nn + no;
#pragma unroll
        for (int i = 0; i < 8; i++) {
            int dd = d0 + ty * 8 + i;
            float v = acc[i][q];
            if (bias) v = __fadd_rn(v, bias[dd]);
            obase[(size_t)dd * Nn] = v;
        }
    }
}

__global__ __launch_bounds__(128) void gemm_k(
    const float* __restrict__ A, const float* __restrict__ W,
    const float* __restrict__ bias, float* __restrict__ out, int Cin, int Cout)
{
    gemm_body(A, W, bias, out, Cin, Cout);
}

// Batched q/k/v GEMMs for BOTH sca branches (independent): z=0..5.
// z0: q_av(x), z1: k_av(y), z2: v_av(y), z3: q_va(y), z4: k_va(x), z5: v_va(x).
__global__ __launch_bounds__(128) void gemm6_k(
    const float* __restrict__ x, const float* __restrict__ y,
    const float* __restrict__ av_w, const float* __restrict__ va_w)
{
    const int z = blockIdx.z;
    const float* A = (z == 0 || z == 4 || z == 5) ? x : y;
    const float* W = (z < 3) ? av_w + (size_t)z * Cc * Cc
                             : va_w + (size_t)(z - 3) * Cc * Cc;
    gemm_body(A, W, nullptr, g_z + (size_t)z * NC, Cc, Cc);
}

// Batched projection GEMMs: z=0 (av, input s0), z=1 (va, input s1).
__global__ __launch_bounds__(128) void proj2_k(
    const float* __restrict__ av_w, const float* __restrict__ va_w)
{
    const int z = blockIdx.z;
    gemm_body(g_s + (size_t)z * NC, (z ? va_w : av_w) + (size_t)3 * Cc * Cc,
              nullptr, g_z + (size_t)z * NC, Cc, Cc);
}

// Batched fc GEMMs: z=0 fc1(x1), z=1 fc2(y1) -> g_z[z].
__global__ __launch_bounds__(128) void fc2g_k(
    const float* __restrict__ fc1_w, const float* __restrict__ fc1_b,
    const float* __restrict__ fc2_w, const float* __restrict__ fc2_b)
{
    const int z = blockIdx.z;
    gemm_body(z ? g_y1 : g_x1, z ? fc2_w : fc1_w, z ? fc2_b : fc1_b,
              g_z + (size_t)z * NC, Cc, Cc);
}

// cur = LIF(zx + zy): identical rounding to reference ((acc+b1)+(acc2+b2)).
__global__ __launch_bounds__(256) void cur_k()
{
    int idx = blockIdx.x * 256 + threadIdx.x;
    float v = __fadd_rn(g_z[idx], g_z[(size_t)NC + idx]);
    g_cur[idx] = (v >= 1.f) ? 1.f : 0.f;
}

// ---------------- XLA:GPU row-reduction replica (mean + var fused) ----------
__global__ __launch_bounds__(224) void stats_k(const float* __restrict__ zb, int Cout)
{
    const int cg = blockIdx.x;
    const int buf = cg / Cout;
    const int ch = cg - buf * Cout;
    const int t = threadIdx.x;
    __shared__ float sw[7];
    __shared__ float smu;
    const int lane = t & 31, w = t >> 5;
    const float* base = zb + (size_t)buf * TBm * Cout * Nn + (size_t)ch * Nn + t;

    // ---- mean ----
    float p = 0.f;
    if (t < Nn)
        for (int m = 0; m < TBm; ++m)
            p = __fadd_rn(p, base[(size_t)m * Cout * Nn]);
#pragma unroll
    for (int off = 16; off; off >>= 1)
        p = __fadd_rn(p, __shfl_down_sync(0xFFFFFFFFu, p, off));
    if (!lane) sw[w] = p;
    __syncthreads();
    if (w == 0) {
        float v = (lane < 7) ? sw[lane] : 0.f;
#pragma unroll
        for (int off = 16; off; off >>= 1)
            v = __fadd_rn(v, __shfl_down_sync(0xFFFFFFFFu, v, off));
        if (!lane) { smu = __fdiv_rn(v, 6272.f); g_mu[cg] = smu; }
    }
    __syncthreads();
    const float mu = smu;

    // ---- var ----
    p = 0.f;
    if (t < Nn)
        for (int m = 0; m < TBm; ++m) {
            float dv = __fsub_rn(base[(size_t)m * Cout * Nn], mu);
            p = __fadd_rn(p, __fmul_rn(dv, dv));
        }
#pragma unroll
    for (int off = 16; off; off >>= 1)
        p = __fadd_rn(p, __shfl_down_sync(0xFFFFFFFFu, p, off));
    __syncthreads();
    if (!lane) sw[w] = p;
    __syncthreads();
    if (w == 0) {
        float v = (lane < 7) ? sw[lane] : 0.f;
#pragma unroll
        for (int off = 16; off; off >>= 1)
            v = __fadd_rn(v, __shfl_down_sync(0xFFFFFFFFu, v, off));
        if (!lane) {
            float var = __fdiv_rn(v, 6272.f);
            g_rs[cg] = rsqrtf(__fadd_rn(var, EPSV));
        }
    }
}

// ---------------- batched BN+LIF -> 16-bit head masks for all 6 branches -------
__global__ __launch_bounds__(256) void mask6_k(
    const float* __restrict__ av_g, const float* __restrict__ av_b,
    const float* __restrict__ va_g, const float* __restrict__ va_b)
{
    const int z = blockIdx.y;
    const float* G  = (z < 3) ? av_g + z * Cc : va_g + (z - 3) * Cc;
    const float* Bt = (z < 3) ? av_b + z * Cc : va_b + (z - 3) * Cc;
    const float* zbuf = g_z + (size_t)z * NC;
    const int muoff = z * Cc;
    int idx = blockIdx.x * 256 + threadIdx.x;     // MASKN threads
    int n  = idx % Nn;
    int th = idx / Nn;
    int h  = th & 15;
    int m  = th >> 4;
    const float* zb = zbuf + (size_t)m * Cc * Nn + (size_t)h * Dd * Nn + n;
    unsigned int msk = 0;
#pragma unroll
    for (int d = 0; d < Dd; ++d) {
        int c = h * Dd + d;
        float bn = bn_val(zb[(size_t)d * Nn], G[c], g_mu[muoff + c], g_rs[muoff + c], Bt[c]);
        if (bn >= 1.f) msk |= (1u << d);
    }
    g_mask[(size_t)z * MASKN + idx] = msk;
}

// ---------------- BN+LIF elementwise (single buffer; optional residual) --------
__global__ __launch_bounds__(256) void spike_bn_k(
    const float* __restrict__ z, const float* __restrict__ g,
    const float* __restrict__ b, const float* __restrict__ addsrc,
    float* __restrict__ out, int Cout)
{
    int idx = blockIdx.x * 256 + threadIdx.x;
    int c = (idx / Nn) % Cout;
    float bn = bn_val(z[idx], g[c], g_mu[c], g_rs[c], b[c]);
    float s = (bn >= 1.f) ? 1.f : 0.f;
    out[idx] = addsrc ? __fadd_rn(addsrc[idx], s) : s;
}

// ---------------- batched BN+LIF + residual for both proj branches -------------
__global__ __launch_bounds__(256) void bn2_k(
    const float* __restrict__ xin, const float* __restrict__ yin,
    const float* __restrict__ av_g, const float* __restrict__ av_b,
    const float* __restrict__ va_g, const float* __restrict__ va_b)
{
    const int z = blockIdx.y;
    const float* G  = (z ? va_g : av_g) + 3 * Cc;
    const float* Bt = (z ? va_b : av_b) + 3 * Cc;
    const float* addsrc = z ? yin : xin;
    float* outp = z ? g_y1 : g_x1;
    const float* zin = g_z + (size_t)z * NC;
    const int muoff = z * Cc;
    int idx = blockIdx.x * 256 + threadIdx.x;
    int c = (idx / Nn) % Cc;
    float bn = bn_val(zin[idx], G[c], g_mu[muoff + c], g_rs[muoff + c], Bt[c]);
    float s = (bn >= 1.f) ? 1.f : 0.f;
    outp[idx] = __fadd_rn(addsrc[idx], s);
}

// ---------------- attention (both branches batched): bitset algebra, exact ------
// z=0: acc_d = sum_b q_b * M[b][d], M[b][d] = sum_m km[m,b]&v[m,d]  (exact ints)
// z=1: per-row attend bitmap over m, then acc_d = sum_w popc(ab[w] & vb[d][w]).
// All integer; rpb compare identical to reference order/values -> bit-exact.
__global__ __launch_bounds__(224) void attn2_k(const float* __restrict__ P)
{
    const int z = blockIdx.y;             // 0: av (no rpb), 1: va (rpb)
    const unsigned int* qm = g_mask + (size_t)(3 * z + 0) * MASKN;
    const unsigned int* km = g_mask + (size_t)(3 * z + 1) * MASKN;
    const unsigned int* vm = g_mask + (size_t)(3 * z + 2) * MASKN;
    float* out = g_s + (size_t)z * NC;

    __shared__ unsigned int skm[Nn];      // k masks (z=1 path)
    __shared__ unsigned int skb[16][8];   // k bit-planes over m (7 words + pad)
    __shared__ unsigned int svb[16][8];   // v bit-planes over m
    __shared__ unsigned int Mp[16][8];    // z=0: packed count matrix (2 d per u32)
    __shared__ float sP[29 * 29];
    const int tbh = blockIdx.x;
    const int mb = tbh >> 4;
    const int h  = tbh & 15;
    const int base = tbh * Nn;
    const int t = threadIdx.x;
    const int warp = t >> 5, lane = t & 31;

    unsigned int myk = 0, myv = 0;
    if (t < Nn) { myk = km[base + t]; myv = vm[base + t]; skm[t] = myk; }
    // bit-planes via ballot: word w covers m in [32w, 32w+32)
#pragma unroll
    for (int b = 0; b < 16; ++b) {
        unsigned int kb = __ballot_sync(0xFFFFFFFFu, (myk >> b) & 1u);
        unsigned int vb = __ballot_sync(0xFFFFFFFFu, (myv >> b) & 1u);
        if (lane == 0) { skb[b][warp] = kb; svb[b][warp] = vb; }
    }
    if (z)
        for (int i = t; i < 841; i += 224) sP[i] = P[i];
    __syncthreads();

    if (z == 0) {
        // build M: thread (b,w) for t<128
        if (t < 128) {
            const int b = t >> 3, w = t & 7;
            unsigned int lo = 0, hi = 0;
#pragma unroll
            for (int j = 0; j < 7; ++j) {
                lo += __popc(skb[b][j] & svb[2*w][j]);
                hi += __popc(skb[b][j] & svb[2*w + 1][j]);
            }
            Mp[b][w] = lo | (hi << 16);
        }
        __syncthreads();
        if (t >= Nn) return;
        const unsigned int q = qm[base + t];
        unsigned int acc[8] = {0,0,0,0,0,0,0,0};
#pragma unroll
        for (int b = 0; b < 16; ++b) {
            unsigned int msk = 0u - ((q >> b) & 1u);
            uint4 m0 = *reinterpret_cast<const uint4*>(&Mp[b][0]);
            uint4 m1 = *reinterpret_cast<const uint4*>(&Mp[b][4]);
            acc[0] += m0.x & msk; acc[1] += m0.y & msk;
            acc[2] += m0.z & msk; acc[3] += m0.w & msk;
            acc[4] += m1.x & msk; acc[5] += m1.y & msk;
            acc[6] += m1.z & msk; acc[7] += m1.w & msk;
        }
        float* obase = out + (size_t)mb * Cc * Nn + (size_t)h * Dd * Nn + t;
#pragma unroll
        for (int w = 0; w < 8; ++w) {
            int lo = (int)(acc[w] & 0xFFFFu);
            int hi = (int)(acc[w] >> 16);
            obase[(size_t)(2*w)     * Nn] = (lo >= 2) ? 1.f : 0.f;  // o*0.25>=0.5
            obase[(size_t)(2*w + 1) * Nn] = (hi >= 2) ? 1.f : 0.f;
        }
    } else {
        if (t >= Nn) return;
        const unsigned int q = qm[base + t];
        const int ni = t / 14, nj = t - (t / 14) * 14;
        const float* prow = sP + (ni + 14) * 29 + (nj + 14);
        unsigned int ab[7] = {0,0,0,0,0,0,0};
#pragma unroll
        for (int ki = 0; ki < 14; ++ki) {
            const float* pr = prow - ki * 29;
#pragma unroll
            for (int kj = 0; kj < 14; ++kj) {
                const int m = ki * 14 + kj;
                int cnt = __popc(q & skm[m]);
                if (__fadd_rn((float)cnt, pr[-kj]) >= 1.f)
                    ab[m >> 5] |= (1u << (m & 31));
            }
        }
        float* obase = out + (size_t)mb * Cc * Nn + (size_t)h * Dd * Nn + t;
#pragma unroll
        for (int w = 0; w < 8; ++w) {
            int lo = 0, hi = 0;
#pragma unroll
            for (int j = 0; j < 7; ++j) {
                lo += __popc(ab[j] & svb[2*w][j]);
                hi += __popc(ab[j] & svb[2*w + 1][j]);
            }
            obase[(size_t)(2*w)     * Nn] = (lo >= 2) ? 1.f : 0.f;
            obase[(size_t)(2*w + 1) * Nn] = (hi >= 2) ? 1.f : 0.f;
        }
    }
}

// ---------------- host orchestration ----------------
extern "C" void kernel_launch(void* const* d_in, const int* in_sizes, int n_in,
                              void* d_out, int out_size)
{
    const float* x     = (const float*)d_in[0];
    const float* y     = (const float*)d_in[1];
    const float* av_w  = (const float*)d_in[2];
    const float* av_g  = (const float*)d_in[3];
    const float* av_b  = (const float*)d_in[4];
    const float* va_w  = (const float*)d_in[5];
    const float* va_g  = (const float*)d_in[6];
    const float* va_b  = (const float*)d_in[7];
    const float* P_rpb = (const float*)d_in[8];
    const float* fc1_w = (const float*)d_in[9];
    const float* fc1_b = (const float*)d_in[10];
    const float* fc2_w = (const float*)d_in[11];
    const float* fc2_b = (const float*)d_in[12];
    const float* m1_w  = (const float*)d_in[13];
    const float* m1_b  = (const float*)d_in[14];
    const float* m1_g  = (const float*)d_in[15];
    const float* m1_bb = (const float*)d_in[16];
    const float* m2_w  = (const float*)d_in[17];
    const float* m2_b  = (const float*)d_in[18];
    const float* m2_g  = (const float*)d_in[19];
    const float* m2_bb = (const float*)d_in[20];
    float* out = (float*)d_out;

    float *zb, *hb, *curb;
    cudaGetSymbolAddress((void**)&zb,  g_z);
    cudaGetSymbolAddress((void**)&hb,  g_h);
    cudaGetSymbolAddress((void**)&curb, g_cur);

    // ---- phase 1: all six q/k/v convs (both sca branches), batched ----
    gemm6_k<<<dim3(98, 4, 6), 128>>>(x, y, av_w, va_w);
    stats_k<<<6 * Cc, 224>>>(zb, Cc);
    mask6_k<<<dim3(392, 6), 256>>>(av_g, av_b, va_g, va_b);

    // ---- phase 2: both attentions, batched ----
    attn2_k<<<dim3(TBm * Hh, 2), 224>>>(P_rpb);

    // ---- phase 3: both projection convs + BN + LIF + residual ----
    proj2_k<<<dim3(98, 4, 2), 128>>>(av_w, va_w);
    stats_k<<<2 * Cc, 224>>>(zb, Cc);
    bn2_k<<<dim3(NC / 256, 2), 256>>>(x, y, av_g, av_b, va_g, va_b);

    // ---- cur = LIF(fc1(x1) + fc2(y1)) : batched GEMMs + fused add/LIF ----
    fc2g_k<<<dim3(98, 4, 2), 128>>>(fc1_w, fc1_b, fc2_w, fc2_b);
    cur_k<<<NC / 256, 256>>>();

    // ---- h = LIF(BN(m1(cur))) ----
    gemm_k<<<dim3(98, 16), 128>>>(curb, m1_w, m1_b, zb, Cc, HDd);
    stats_k<<<HDd, 224>>>(zb, HDd);
    spike_bn_k<<<NHD / 256, 256>>>(zb, m1_g, m1_bb, nullptr, hb, HDd);

    // ---- out = cur + LIF(BN(m2(h))) ----
    gemm_k<<<dim3(98, 4), 128>>>(hb, m2_w, m2_b, zb, HDd, Cc);
    stats_k<<<Cc, 224>>>(zb, Cc);
    spike_bn_k<<<NC / 256, 256>>>(zb, m2_g, m2_bb, curb, out, Cc);

    (void)in_sizes; (void)n_in; (void)out_size;
}

// round 17
// speedup vs baseline: 1.6760x; 1.6760x over previous
#include <cuda_runtime.h>

// Problem constants
#define TBm 32       // T*B
#define Cc  256
#define Nn  196
#define Hh  16
#define Dd  16
#define HDd 1024
#define Jj  (TBm*Nn)        // 6272
#define NC  (TBm*Cc*Nn)     // 1,605,632
#define NHD (TBm*HDd*Nn)    // 6,422,528
#define MASKN (TBm*Hh*Nn)   // 100,352
#define EPSV 1e-5f

// ---------------- scratch (static device globals; no runtime alloc) -------------
__device__ float g_z [6*NC];         // 6 qkv buffers; also >= NHD for m1 scratch
__device__ float g_h [NHD];          // h spikes (m1 output)
__device__ float g_s [2*NC];         // attention o spikes (both sca branches)
__device__ float g_x1[NC];
__device__ float g_y1[NC];
__device__ float g_cur[NC];
__device__ unsigned int g_mask[6*MASKN];
__device__ float g_mu[6*Cc >= HDd ? 6*Cc : HDd];
__device__ float g_rs[6*Cc >= HDd ? 6*Cc : HDd];

// BN affine exactly as reference: ((g*(z-mu))*rs)+b, separate roundings
__device__ __forceinline__ float bn_val(float v, float g, float mu, float rs, float b)
{
    return __fadd_rn(__fmul_rn(__fmul_rn(g, __fsub_rn(v, mu)), rs), b);
}

// ---------------- GEMM core: out[m,d,n] = sum_c W[d,c]*A[m,c,n] ----------------
// Exact fp32, strictly ascending-k single-accumulator FMA per output element.
// Tile 64(d) x 64(j), BK=16, 128 threads, 8x4 per thread; register prefetch.
__device__ __forceinline__ void gemm_body(
    const float* __restrict__ A, const float* __restrict__ W,
    const float* __restrict__ bias,
    float* __restrict__ out, int Cin, int Cout)
{
    __shared__ float As[16][68];
    __shared__ float Bs[16][68];
    const int t  = threadIdx.x;
    const int d0 = blockIdx.y * 64;
    const int j0 = blockIdx.x * 64;
    const int tx = t & 15;           // j group: j = j0 + tx*4 .. +3
    const int ty = t >> 4;           // d group: d = d0 + ty*8 .. +7
    const int jj = t & 63;
    const int kr = t >> 6;           // 0..1  (k rows kr + 2*r, r<8)
    const int jB = j0 + jj;
    const int mB = jB / Nn;
    const int nB = jB - mB * Nn;
    const int kc = t & 15;           // k column
    const int dr = t >> 4;           // 0..7  (d rows dr + 8*r, r<8)

    float acc[8][4];
#pragma unroll
    for (int i = 0; i < 8; i++)
#pragma unroll
        for (int q = 0; q < 4; q++) acc[i][q] = 0.f;

    float wreg[8], breg[8];
    const float* aptr = A + (size_t)mB * Cin * Nn + nB;
    const int nst = Cin >> 4;

    // prefetch stage 0
#pragma unroll
    for (int r = 0; r < 8; ++r)
        wreg[r] = W[(size_t)(d0 + dr + 8*r) * Cin + kc];
#pragma unroll
    for (int r = 0; r < 8; ++r)
        breg[r] = aptr[(size_t)(kr + 2*r) * Nn];

#pragma unroll 1
    for (int s = 0; s < nst; ++s) {
        __syncthreads();
#pragma unroll
        for (int r = 0; r < 8; ++r) As[kc][dr + 8*r] = wreg[r];
#pragma unroll
        for (int r = 0; r < 8; ++r) Bs[kr + 2*r][jj] = breg[r];
        __syncthreads();

        if (s + 1 < nst) {
            const int c0 = (s + 1) << 4;
#pragma unroll
            for (int r = 0; r < 8; ++r)
                wreg[r] = W[(size_t)(d0 + dr + 8*r) * Cin + c0 + kc];
#pragma unroll
            for (int r = 0; r < 8; ++r)
                breg[r] = aptr[(size_t)(c0 + kr + 2*r) * Nn];
        }
#pragma unroll
        for (int k = 0; k < 16; ++k) {
            float4 a0 = *reinterpret_cast<const float4*>(&As[k][ty * 8]);
            float4 a1 = *reinterpret_cast<const float4*>(&As[k][ty * 8 + 4]);
            float4 b4 = *reinterpret_cast<const float4*>(&Bs[k][tx * 4]);
            float a[8] = {a0.x, a0.y, a0.z, a0.w, a1.x, a1.y, a1.z, a1.w};
            float b[4] = {b4.x, b4.y, b4.z, b4.w};
#pragma unroll
            for (int i = 0; i < 8; i++)
#pragma unroll
                for (int q = 0; q < 4; q++)
                    acc[i][q] = __fmaf_rn(a[i], b[q], acc[i][q]);
        }
    }
#pragma unroll
    for (int q = 0; q < 4; q++) {
        int jw = j0 + tx * 4 + q;
        int mo = jw / Nn;
        int no = jw - mo * Nn;
        float* obase = out + (size_t)mo * Cout * Nn + no;
#pragma unroll
        for (int i = 0; i < 8; i++) {
            int dd = d0 + ty * 8 + i;
            float v = acc[i][q];
            if (bias) v = __fadd_rn(v, bias[dd]);
            obase[(size_t)dd * Nn] = v;
        }
    }
}

__global__ __launch_bounds__(128) void gemm_k(
    const float* __restrict__ A, const float* __restrict__ W,
    const float* __restrict__ bias, float* __restrict__ out, int Cin, int Cout)
{
    gemm_body(A, W, bias, out, Cin, Cout);
}

// Batched q/k/v GEMMs for BOTH sca branches (independent): z=0..5.
// z0: q_av(x), z1: k_av(y), z2: v_av(y), z3: q_va(y), z4: k_va(x), z5: v_va(x).
__global__ __launch_bounds__(128) void gemm6_k(
    const float* __restrict__ x, const float* __restrict__ y,
    const float* __restrict__ av_w, const float* __restrict__ va_w)
{
    const int z = blockIdx.z;
    const float* A = (z == 0 || z == 4 || z == 5) ? x : y;
    const float* W = (z < 3) ? av_w + (size_t)z * Cc * Cc
                             : va_w + (size_t)(z - 3) * Cc * Cc;
    gemm_body(A, W, nullptr, g_z + (size_t)z * NC, Cc, Cc);
}

// Batched projection GEMMs: z=0 (av, input s0), z=1 (va, input s1).
__global__ __launch_bounds__(128) void proj2_k(
    const float* __restrict__ av_w, const float* __restrict__ va_w)
{
    const int z = blockIdx.z;
    gemm_body(g_s + (size_t)z * NC, (z ? va_w : av_w) + (size_t)3 * Cc * Cc,
              nullptr, g_z + (size_t)z * NC, Cc, Cc);
}

// Batched fc GEMMs: z=0 fc1(x1), z=1 fc2(y1) -> g_z[z].
__global__ __launch_bounds__(128) void fc2g_k(
    const float* __restrict__ fc1_w, const float* __restrict__ fc1_b,
    const float* __restrict__ fc2_w, const float* __restrict__ fc2_b)
{
    const int z = blockIdx.z;
    gemm_body(z ? g_y1 : g_x1, z ? fc2_w : fc1_w, z ? fc2_b : fc1_b,
              g_z + (size_t)z * NC, Cc, Cc);
}

// cur = LIF(zx + zy), float4: identical rounding ((acc+b1)+(acc2+b2)).
__global__ __launch_bounds__(256) void cur_k()
{
    int i4 = blockIdx.x * 256 + threadIdx.x;     // NC/4 threads
    const float4 a = reinterpret_cast<const float4*>(g_z)[i4];
    const float4 b = reinterpret_cast<const float4*>(g_z + NC)[i4];
    float4 o;
    o.x = (__fadd_rn(a.x, b.x) >= 1.f) ? 1.f : 0.f;
    o.y = (__fadd_rn(a.y, b.y) >= 1.f) ? 1.f : 0.f;
    o.z = (__fadd_rn(a.z, b.z) >= 1.f) ? 1.f : 0.f;
    o.w = (__fadd_rn(a.w, b.w) >= 1.f) ? 1.f : 0.f;
    reinterpret_cast<float4*>(g_cur)[i4] = o;
}

// ---------------- XLA:GPU row-reduction replica (mean + var fused) ----------
__global__ __launch_bounds__(224) void stats_k(const float* __restrict__ zb, int Cout)
{
    const int cg = blockIdx.x;
    const int buf = cg / Cout;
    const int ch = cg - buf * Cout;
    const int t = threadIdx.x;
    __shared__ float sw[7];
    __shared__ float smu;
    const int lane = t & 31, w = t >> 5;
    const float* base = zb + (size_t)buf * TBm * Cout * Nn + (size_t)ch * Nn + t;

    // ---- mean ----
    float p = 0.f;
    if (t < Nn)
        for (int m = 0; m < TBm; ++m)
            p = __fadd_rn(p, base[(size_t)m * Cout * Nn]);
#pragma unroll
    for (int off = 16; off; off >>= 1)
        p = __fadd_rn(p, __shfl_down_sync(0xFFFFFFFFu, p, off));
    if (!lane) sw[w] = p;
    __syncthreads();
    if (w == 0) {
        float v = (lane < 7) ? sw[lane] : 0.f;
#pragma unroll
        for (int off = 16; off; off >>= 1)
            v = __fadd_rn(v, __shfl_down_sync(0xFFFFFFFFu, v, off));
        if (!lane) { smu = __fdiv_rn(v, 6272.f); g_mu[cg] = smu; }
    }
    __syncthreads();
    const float mu = smu;

    // ---- var ----
    p = 0.f;
    if (t < Nn)
        for (int m = 0; m < TBm; ++m) {
            float dv = __fsub_rn(base[(size_t)m * Cout * Nn], mu);
            p = __fadd_rn(p, __fmul_rn(dv, dv));
        }
#pragma unroll
    for (int off = 16; off; off >>= 1)
        p = __fadd_rn(p, __shfl_down_sync(0xFFFFFFFFu, p, off));
    __syncthreads();
    if (!lane) sw[w] = p;
    __syncthreads();
    if (w == 0) {
        float v = (lane < 7) ? sw[lane] : 0.f;
#pragma unroll
        for (int off = 16; off; off >>= 1)
            v = __fadd_rn(v, __shfl_down_sync(0xFFFFFFFFu, v, off));
        if (!lane) {
            float var = __fdiv_rn(v, 6272.f);
            g_rs[cg] = rsqrtf(__fadd_rn(var, EPSV));
        }
    }
}

// ---------------- batched BN+LIF -> 16-bit head masks for all 6 branches -------
__global__ __launch_bounds__(256) void mask6_k(
    const float* __restrict__ av_g, const float* __restrict__ av_b,
    const float* __restrict__ va_g, const float* __restrict__ va_b)
{
    const int z = blockIdx.y;
    const float* G  = (z < 3) ? av_g + z * Cc : va_g + (z - 3) * Cc;
    const float* Bt = (z < 3) ? av_b + z * Cc : va_b + (z - 3) * Cc;
    const float* zbuf = g_z + (size_t)z * NC;
    const int muoff = z * Cc;
    int idx = blockIdx.x * 256 + threadIdx.x;     // MASKN threads
    int n  = idx % Nn;
    int th = idx / Nn;
    int h  = th & 15;
    int m  = th >> 4;
    const float* zb = zbuf + (size_t)m * Cc * Nn + (size_t)h * Dd * Nn + n;
    unsigned int msk = 0;
#pragma unroll
    for (int d = 0; d < Dd; ++d) {
        int c = h * Dd + d;
        float bn = bn_val(zb[(size_t)d * Nn], G[c], g_mu[muoff + c], g_rs[muoff + c], Bt[c]);
        if (bn >= 1.f) msk |= (1u << d);
    }
    g_mask[(size_t)z * MASKN + idx] = msk;
}

// ---------------- BN+LIF elementwise, float4 (optional residual) ---------------
__global__ __launch_bounds__(256) void spike_bn_k(
    const float* __restrict__ z, const float* __restrict__ g,
    const float* __restrict__ b, const float* __restrict__ addsrc,
    float* __restrict__ out, int Cout)
{
    int i4 = blockIdx.x * 256 + threadIdx.x;     // N/4 threads
    int idx = i4 * 4;
    int c = (idx / Nn) % Cout;                   // 4 consecutive n share channel
    const float gc = g[c], mc = g_mu[c], rc = g_rs[c], bc = b[c];
    float4 v = reinterpret_cast<const float4*>(z)[i4];
    float4 o;
    o.x = (bn_val(v.x, gc, mc, rc, bc) >= 1.f) ? 1.f : 0.f;
    o.y = (bn_val(v.y, gc, mc, rc, bc) >= 1.f) ? 1.f : 0.f;
    o.z = (bn_val(v.z, gc, mc, rc, bc) >= 1.f) ? 1.f : 0.f;
    o.w = (bn_val(v.w, gc, mc, rc, bc) >= 1.f) ? 1.f : 0.f;
    if (addsrc) {
        float4 a = reinterpret_cast<const float4*>(addsrc)[i4];
        o.x = __fadd_rn(a.x, o.x); o.y = __fadd_rn(a.y, o.y);
        o.z = __fadd_rn(a.z, o.z); o.w = __fadd_rn(a.w, o.w);
    }
    reinterpret_cast<float4*>(out)[i4] = o;
}

// ---------------- batched BN+LIF + residual for both proj branches, float4 -----
__global__ __launch_bounds__(256) void bn2_k(
    const float* __restrict__ xin, const float* __restrict__ yin,
    const float* __restrict__ av_g, const float* __restrict__ av_b,
    const float* __restrict__ va_g, const float* __restrict__ va_b)
{
    const int z = blockIdx.y;
    const float* G  = (z ? va_g : av_g) + 3 * Cc;
    const float* Bt = (z ? va_b : av_b) + 3 * Cc;
    const float* addsrc = z ? yin : xin;
    float* outp = z ? g_y1 : g_x1;
    const float* zin = g_z + (size_t)z * NC;
    const int muoff = z * Cc;
    int i4 = blockIdx.x * 256 + threadIdx.x;     // NC/4 threads
    int idx = i4 * 4;
    int c = (idx / Nn) % Cc;
    const float gc = G[c], mc = g_mu[muoff + c], rc = g_rs[muoff + c], bc = Bt[c];
    float4 v = reinterpret_cast<const float4*>(zin)[i4];
    float4 a = reinterpret_cast<const float4*>(addsrc)[i4];
    float4 o;
    o.x = __fadd_rn(a.x, (bn_val(v.x, gc, mc, rc, bc) >= 1.f) ? 1.f : 0.f);
    o.y = __fadd_rn(a.y, (bn_val(v.y, gc, mc, rc, bc) >= 1.f) ? 1.f : 0.f);
    o.z = __fadd_rn(a.z, (bn_val(v.z, gc, mc, rc, bc) >= 1.f) ? 1.f : 0.f);
    o.w = __fadd_rn(a.w, (bn_val(v.w, gc, mc, rc, bc) >= 1.f) ? 1.f : 0.f);
    reinterpret_cast<float4*>(outp)[i4] = o;
}

// ---------------- attention (both branches batched): bitset algebra, exact ------
// z=0: acc_d = sum_b q_b * M[b][d], M[b][d] = sum_m km[m,b]&v[m,d]  (exact ints)
// z=1: per-row attend bitmap over m, then acc_d = sum_w popc(ab[w] & vb[d][w]).
// All integer; rpb compare identical to reference order/values -> bit-exact.
__global__ __launch_bounds__(224) void attn2_k(const float* __restrict__ P)
{
    const int z = blockIdx.y;             // 0: av (no rpb), 1: va (rpb)
    const unsigned int* qm = g_mask + (size_t)(3 * z + 0) * MASKN;
    const unsigned int* km = g_mask + (size_t)(3 * z + 1) * MASKN;
    const unsigned int* vm = g_mask + (size_t)(3 * z + 2) * MASKN;
    float* out = g_s + (size_t)z * NC;

    __shared__ unsigned int skm[Nn];      // k masks (z=1 path)
    __shared__ unsigned int skb[16][8];   // k bit-planes over m (7 words + pad)
    __shared__ unsigned int svb[16][8];   // v bit-planes over m
    __shared__ unsigned int Mp[16][8];    // z=0: packed count matrix (2 d per u32)
    __shared__ float sP[29 * 29];
    const int tbh = blockIdx.x;
    const int mb = tbh >> 4;
    const int h  = tbh & 15;
    const int base = tbh * Nn;
    const int t = threadIdx.x;
    const int warp = t >> 5, lane = t & 31;

    unsigned int myk = 0, myv = 0;
    if (t < Nn) { myk = km[base + t]; myv = vm[base + t]; skm[t] = myk; }
    // bit-planes via ballot: word w covers m in [32w, 32w+32)
#pragma unroll
    for (int b = 0; b < 16; ++b) {
        unsigned int kb = __ballot_sync(0xFFFFFFFFu, (myk >> b) & 1u);
        unsigned int vb = __ballot_sync(0xFFFFFFFFu, (myv >> b) & 1u);
        if (lane == 0) { skb[b][warp] = kb; svb[b][warp] = vb; }
    }
    if (z)
        for (int i = t; i < 841; i += 224) sP[i] = P[i];
    __syncthreads();

    if (z == 0) {
        // build M: thread (b,w) for t<128
        if (t < 128) {
            const int b = t >> 3, w = t & 7;
            unsigned int lo = 0, hi = 0;
#pragma unroll
            for (int j = 0; j < 7; ++j) {
                lo += __popc(skb[b][j] & svb[2*w][j]);
                hi += __popc(skb[b][j] & svb[2*w + 1][j]);
            }
            Mp[b][w] = lo | (hi << 16);
        }
        __syncthreads();
        if (t >= Nn) return;
        const unsigned int q = qm[base + t];
        unsigned int acc[8] = {0,0,0,0,0,0,0,0};
#pragma unroll
        for (int b = 0; b < 16; ++b) {
            unsigned int msk = 0u - ((q >> b) & 1u);
            uint4 m0 = *reinterpret_cast<const uint4*>(&Mp[b][0]);
            uint4 m1 = *reinterpret_cast<const uint4*>(&Mp[b][4]);
            acc[0] += m0.x & msk; acc[1] += m0.y & msk;
            acc[2] += m0.z & msk; acc[3] += m0.w & msk;
            acc[4] += m1.x & msk; acc[5] += m1.y & msk;
            acc[6] += m1.z & msk; acc[7] += m1.w & msk;
        }
        float* obase = out + (size_t)mb * Cc * Nn + (size_t)h * Dd * Nn + t;
#pragma unroll
        for (int w = 0; w < 8; ++w) {
            int lo = (int)(acc[w] & 0xFFFFu);
            int hi = (int)(acc[w] >> 16);
            obase[(size_t)(2*w)     * Nn] = (lo >= 2) ? 1.f : 0.f;  // o*0.25>=0.5
            obase[(size_t)(2*w + 1) * Nn] = (hi >= 2) ? 1.f : 0.f;
        }
    } else {
        if (t >= Nn) return;
        const unsigned int q = qm[base + t];
        const int ni = t / 14, nj = t - (t / 14) * 14;
        const float* prow = sP + (ni + 14) * 29 + (nj + 14);
        unsigned int ab[7] = {0,0,0,0,0,0,0};
#pragma unroll
        for (int ki = 0; ki < 14; ++ki) {
            const float* pr = prow - ki * 29;
#pragma unroll
            for (int kj = 0; kj < 14; ++kj) {
                const int m = ki * 14 + kj;
                int cnt = __popc(q & skm[m]);
                if (__fadd_rn((float)cnt, pr[-kj]) >= 1.f)
                    ab[m >> 5] |= (1u << (m & 31));
            }
        }
        float* obase = out + (size_t)mb * Cc * Nn + (size_t)h * Dd * Nn + t;
#pragma unroll
        for (int w = 0; w < 8; ++w) {
            int lo = 0, hi = 0;
#pragma unroll
            for (int j = 0; j < 7; ++j) {
                lo += __popc(ab[j] & svb[2*w][j]);
                hi += __popc(ab[j] & svb[2*w + 1][j]);
            }
            obase[(size_t)(2*w)     * Nn] = (lo >= 2) ? 1.f : 0.f;
            obase[(size_t)(2*w + 1) * Nn] = (hi >= 2) ? 1.f : 0.f;
        }
    }
}

// ---------------- host orchestration ----------------
extern "C" void kernel_launch(void* const* d_in, const int* in_sizes, int n_in,
                              void* d_out, int out_size)
{
    const float* x     = (const float*)d_in[0];
    const float* y     = (const float*)d_in[1];
    const float* av_w  = (const float*)d_in[2];
    const float* av_g  = (const float*)d_in[3];
    const float* av_b  = (const float*)d_in[4];
    const float* va_w  = (const float*)d_in[5];
    const float* va_g  = (const float*)d_in[6];
    const float* va_b  = (const float*)d_in[7];
    const float* P_rpb = (const float*)d_in[8];
    const float* fc1_w = (const float*)d_in[9];
    const float* fc1_b = (const float*)d_in[10];
    const float* fc2_w = (const float*)d_in[11];
    const float* fc2_b = (const float*)d_in[12];
    const float* m1_w  = (const float*)d_in[13];
    const float* m1_b  = (const float*)d_in[14];
    const float* m1_g  = (const float*)d_in[15];
    const float* m1_bb = (const float*)d_in[16];
    const float* m2_w  = (const float*)d_in[17];
    const float* m2_b  = (const float*)d_in[18];
    const float* m2_g  = (const float*)d_in[19];
    const float* m2_bb = (const float*)d_in[20];
    float* out = (float*)d_out;

    float *zb, *hb, *curb;
    cudaGetSymbolAddress((void**)&zb,  g_z);
    cudaGetSymbolAddress((void**)&hb,  g_h);
    cudaGetSymbolAddress((void**)&curb, g_cur);

    // ---- phase 1: all six q/k/v convs (both sca branches), batched ----
    gemm6_k<<<dim3(98, 4, 6), 128>>>(x, y, av_w, va_w);
    stats_k<<<6 * Cc, 224>>>(zb, Cc);
    mask6_k<<<dim3(392, 6), 256>>>(av_g, av_b, va_g, va_b);

    // ---- phase 2: both attentions, batched ----
    attn2_k<<<dim3(TBm * Hh, 2), 224>>>(P_rpb);

    // ---- phase 3: both projection convs + BN + LIF + residual ----
    proj2_k<<<dim3(98, 4, 2), 128>>>(av_w, va_w);
    stats_k<<<2 * Cc, 224>>>(zb, Cc);
    bn2_k<<<dim3(NC / 1024, 2), 256>>>(x, y, av_g, av_b, va_g, va_b);

    // ---- cur = LIF(fc1(x1) + fc2(y1)) : batched GEMMs + fused add/LIF ----
    fc2g_k<<<dim3(98, 4, 2), 128>>>(fc1_w, fc1_b, fc2_w, fc2_b);
    cur_k<<<NC / 1024, 256>>>();

    // ---- h = LIF(BN(m1(cur))) ----
    gemm_k<<<dim3(98, 16), 128>>>(curb, m1_w, m1_b, zb, Cc, HDd);
    stats_k<<<HDd, 224>>>(zb, HDd);
    spike_bn_k<<<NHD / 1024, 256>>>(zb, m1_g, m1_bb, nullptr, hb, HDd);

    // ---- out = cur + LIF(BN(m2(h))) ----
    gemm_k<<<dim3(98, 4), 128>>>(hb, m2_w, m2_b, zb, HDd, Cc);
    stats_k<<<Cc, 224>>>(zb, Cc);
    spike_bn_k<<<NC / 1024, 256>>>(zb, m2_g, m2_bb, curb, out, Cc);

    (void)in_sizes; (void)n_in; (void)out_size;
}